// round 7
// baseline (speedup 1.0000x reference)
#include <cuda_runtime.h>

// x1, x2: [N, D] fp32, N=8192, D=1024 row-major.
// ort = dot(colsum(x1), colsum(x2)) / (N*N)

static constexpr int D    = 1024;
static constexpr int D4   = D / 4;     // 256 float4 per row
static constexpr int NB   = 592;       // K1 grid = 148 SMs * 4 (one wave)
static constexpr int PH2B = 32;        // K2 grid: 32 blocks, 8 float4-cols each

// Scratch (__device__ globals; no allocation allowed)
__device__ float    g_part1[NB * D];   // 2.42 MB
__device__ float    g_part2[NB * D];   // 2.42 MB
__device__ double   g_acc;
__device__ unsigned g_done = 0;

__device__ __forceinline__ void acc4(float4& a, const float4 v) {
    a.x += v.x; a.y += v.y; a.z += v.z; a.w += v.w;
}

// ── K1: per-block partial column sums (unchanged from R3 — at the LTS cap).
// Each thread owns one float4 column group; 4-row manual unroll gives 8
// batched independent LDG.128 (MLP=8); 2 accumulators break the FADD chain.
__global__ __launch_bounds__(256, 4) void colsum_partials(
    const float4* __restrict__ x1,
    const float4* __restrict__ x2,
    int nrows)
{
    const int t = threadIdx.x;
    const int b = blockIdx.x;

    if (b == 0 && t == 0) { g_acc = 0.0; g_done = 0u; }  // K2 runs after K1

    const size_t stride = (size_t)NB * D4;
    size_t off = (size_t)b * D4 + t;

    float4 a10 = make_float4(0.f,0.f,0.f,0.f), a11 = a10;
    float4 a20 = a10, a21 = a10;

    int r = b;
    for (; r + 3 * NB < nrows; r += 4 * NB, off += 4 * stride) {
        const float4 u0 = __ldg(x1 + off);
        const float4 u1 = __ldg(x1 + off +     stride);
        const float4 u2 = __ldg(x1 + off + 2 * stride);
        const float4 u3 = __ldg(x1 + off + 3 * stride);
        const float4 w0 = __ldg(x2 + off);
        const float4 w1 = __ldg(x2 + off +     stride);
        const float4 w2 = __ldg(x2 + off + 2 * stride);
        const float4 w3 = __ldg(x2 + off + 3 * stride);
        acc4(a10, u0); acc4(a11, u1); acc4(a10, u2); acc4(a11, u3);
        acc4(a20, w0); acc4(a21, w1); acc4(a20, w2); acc4(a21, w3);
    }
    for (; r < nrows; r += NB, off += stride) {
        acc4(a10, __ldg(x1 + off));
        acc4(a20, __ldg(x2 + off));
    }

    acc4(a10, a11);
    acc4(a20, a21);
    ((float4*)g_part1)[(size_t)b * D4 + t] = a10;
    ((float4*)g_part2)[(size_t)b * D4 + t] = a20;
}

// ── K2: finish colsums (coalesced), dot, finalize. 32 blocks x 256 threads.
// Block g owns float4-cols [g*8, g*8+8). Lane layout: col4 = t&7 (8 lanes
// cover one contiguous 128B line), rl = t>>3 strides the 592 partial rows.
__global__ __launch_bounds__(256) void reduce_dot_finalize(
    float* __restrict__ out, double inv_count)
{
    const int t    = threadIdx.x;
    const int g    = blockIdx.x;
    const int col4 = t & 7;
    const int rl   = t >> 3;             // 0..31
    const int cv   = g * 8 + col4;       // global float4 column

    const float4* p1 = (const float4*)g_part1;
    const float4* p2 = (const float4*)g_part2;

    float4 s1 = make_float4(0.f,0.f,0.f,0.f);
    float4 s2 = s1;
    for (int j = rl; j < NB; j += 32) {  // 18-19 iters, L2-resident, coalesced
        acc4(s1, p1[(size_t)j * D4 + cv]);
        acc4(s2, p2[(size_t)j * D4 + cv]);
    }

    // warp reduce over rl (offsets 16, 8 preserve col4 = lane&7)
    #pragma unroll
    for (int o = 16; o >= 8; o >>= 1) {
        s1.x += __shfl_down_sync(0xFFFFFFFFu, s1.x, o);
        s1.y += __shfl_down_sync(0xFFFFFFFFu, s1.y, o);
        s1.z += __shfl_down_sync(0xFFFFFFFFu, s1.z, o);
        s1.w += __shfl_down_sync(0xFFFFFFFFu, s1.w, o);
        s2.x += __shfl_down_sync(0xFFFFFFFFu, s2.x, o);
        s2.y += __shfl_down_sync(0xFFFFFFFFu, s2.y, o);
        s2.z += __shfl_down_sync(0xFFFFFFFFu, s2.z, o);
        s2.w += __shfl_down_sync(0xFFFFFFFFu, s2.w, o);
    }

    __shared__ float4 sh1[8][8], sh2[8][8];   // [warp][col4]
    const int warp = t >> 5, lane = t & 31;
    if (lane < 8) { sh1[warp][lane] = s1; sh2[warp][lane] = s2; }
    __syncthreads();

    if (warp == 0) {
        const int w = lane >> 3, c = lane & 7;   // warps 0..3; fold 4..7 on load
        float4 v1 = sh1[w][c], v2 = sh2[w][c];
        acc4(v1, sh1[w + 4][c]);
        acc4(v2, sh2[w + 4][c]);
        #pragma unroll
        for (int o = 16; o >= 8; o >>= 1) {
            v1.x += __shfl_down_sync(0xFFFFFFFFu, v1.x, o);
            v1.y += __shfl_down_sync(0xFFFFFFFFu, v1.y, o);
            v1.z += __shfl_down_sync(0xFFFFFFFFu, v1.z, o);
            v1.w += __shfl_down_sync(0xFFFFFFFFu, v1.w, o);
            v2.x += __shfl_down_sync(0xFFFFFFFFu, v2.x, o);
            v2.y += __shfl_down_sync(0xFFFFFFFFu, v2.y, o);
            v2.z += __shfl_down_sync(0xFFFFFFFFu, v2.z, o);
            v2.w += __shfl_down_sync(0xFFFFFFFFu, v2.w, o);
        }
        // lanes 0..7 hold COMPLETE colsums for cols g*8 + lane -> dot in double
        double d = (double)v1.x * (double)v2.x
                 + (double)v1.y * (double)v2.y
                 + (double)v1.z * (double)v2.z
                 + (double)v1.w * (double)v2.w;
        #pragma unroll
        for (int o = 4; o > 0; o >>= 1)
            d += __shfl_down_sync(0xFFFFFFFFu, d, o, 8);

        if (lane == 0) {
            atomicAdd(&g_acc, d);
            __threadfence();
            const unsigned dt = atomicAdd(&g_done, 1u);
            if (dt == PH2B - 1)
                out[0] = (float)(*(volatile double*)&g_acc * inv_count);
        }
    }
}

extern "C" void kernel_launch(void* const* d_in, const int* in_sizes, int n_in,
                              void* d_out, int out_size)
{
    const float4* x1 = (const float4*)d_in[0];
    const float4* x2 = (const float4*)d_in[1];
    float* out = (float*)d_out;

    const int rows1 = in_sizes[0] / D;   // 8192
    const int rows2 = in_sizes[1] / D;   // 8192
    const double inv_count = 1.0 / ((double)rows1 * (double)rows2);

    colsum_partials<<<NB, 256>>>(x1, x2, rows1);
    reduce_dot_finalize<<<PH2B, 256>>>(out, inv_count);
}

// round 9
// speedup vs baseline: 1.4634x; 1.4634x over previous
#include <cuda_runtime.h>

// x1, x2: [N, D] fp32, N=8192, D=1024 row-major.
// ort = dot(colsum(x1), colsum(x2)) / (N*N)

static constexpr int D    = 1024;
static constexpr int D4   = D / 4;     // 256 float4 per row
static constexpr int NB   = 592;       // K1 grid = 148 SMs * 4 (one wave)
static constexpr int K2B  = 128;       // K2 grid: 128 blocks, 2 float4-cols each

// Scratch (__device__ globals; no allocation allowed)
__device__ float    g_part1[NB * D];   // 2.42 MB
__device__ float    g_part2[NB * D];   // 2.42 MB
__device__ double   g_acc;
__device__ unsigned g_done = 0;

__device__ __forceinline__ void acc4(float4& a, const float4 v) {
    a.x += v.x; a.y += v.y; a.z += v.z; a.w += v.w;
}

// ── K1: per-block partial column sums (unchanged — at the LTS cap).
// Each thread owns one float4 column group; 4-row manual unroll gives 8
// batched independent LDG.128 (MLP=8); 2 accumulators break the FADD chain.
__global__ __launch_bounds__(256, 4) void colsum_partials(
    const float4* __restrict__ x1,
    const float4* __restrict__ x2,
    int nrows)
{
    const int t = threadIdx.x;
    const int b = blockIdx.x;

    if (b == 0 && t == 0) { g_acc = 0.0; g_done = 0u; }  // K2 ordered after K1

    const size_t stride = (size_t)NB * D4;
    size_t off = (size_t)b * D4 + t;

    float4 a10 = make_float4(0.f,0.f,0.f,0.f), a11 = a10;
    float4 a20 = a10, a21 = a10;

    int r = b;
    for (; r + 3 * NB < nrows; r += 4 * NB, off += 4 * stride) {
        const float4 u0 = __ldg(x1 + off);
        const float4 u1 = __ldg(x1 + off +     stride);
        const float4 u2 = __ldg(x1 + off + 2 * stride);
        const float4 u3 = __ldg(x1 + off + 3 * stride);
        const float4 w0 = __ldg(x2 + off);
        const float4 w1 = __ldg(x2 + off +     stride);
        const float4 w2 = __ldg(x2 + off + 2 * stride);
        const float4 w3 = __ldg(x2 + off + 3 * stride);
        acc4(a10, u0); acc4(a11, u1); acc4(a10, u2); acc4(a11, u3);
        acc4(a20, w0); acc4(a21, w1); acc4(a20, w2); acc4(a21, w3);
    }
    for (; r < nrows; r += NB, off += stride) {
        acc4(a10, __ldg(x1 + off));
        acc4(a20, __ldg(x2 + off));
    }

    acc4(a10, a11);
    acc4(a20, a21);
    ((float4*)g_part1)[(size_t)b * D4 + t] = a10;
    ((float4*)g_part2)[(size_t)b * D4 + t] = a20;
}

// ── K2: finish colsums, dot, finalize. 128 blocks x 256 threads.
// Block g owns float4-cols {g*2, g*2+1}. Lane layout: col = t&1 (lane pairs
// read 32B contiguous = full sector use), rl = t>>1 (128 row-lanes).
// Rows per thread: exactly 5 (592 = 4*128 + 80): 4 unconditional + 1
// predicated, ALL loads issued back-to-back -> one latency exposure.
__global__ __launch_bounds__(256) void reduce_dot_finalize(
    float* __restrict__ out, double inv_count)
{
    const int t   = threadIdx.x;
    const int g   = blockIdx.x;
    const int col = t & 1;
    const int rl  = t >> 1;              // 0..127
    const int cv  = g * 2 + col;         // global float4 column

    const float4* __restrict__ p1 = (const float4*)g_part1;
    const float4* __restrict__ p2 = (const float4*)g_part2;

    const size_t st  = (size_t)128 * D4;           // row stride of 128 rows
    const size_t off = (size_t)rl * D4 + cv;
    const bool tail  = (rl < NB - 512);            // rl < 80 -> 5th row exists
    const size_t off4 = tail ? (off + 4 * st) : off;  // safe dup if no tail

    // 10 independent loads, batched (8 + 2 predicated-by-index)
    const float4 u0 = p1[off];
    const float4 u1 = p1[off +     st];
    const float4 u2 = p1[off + 2 * st];
    const float4 u3 = p1[off + 3 * st];
    const float4 w0 = p2[off];
    const float4 w1 = p2[off +     st];
    const float4 w2 = p2[off + 2 * st];
    const float4 w3 = p2[off + 3 * st];
    float4 u4 = p1[off4];
    float4 w4 = p2[off4];
    if (!tail) { u4 = make_float4(0.f,0.f,0.f,0.f); w4 = u4; }

    float4 s1 = u0, s2 = w0;
    acc4(s1, u1); acc4(s1, u2); acc4(s1, u3); acc4(s1, u4);
    acc4(s2, w1); acc4(s2, w2); acc4(s2, w3); acc4(s2, w4);

    // warp reduce over rl (offsets 16,8,4,2 preserve col = lane&1)
    #pragma unroll
    for (int o = 16; o >= 2; o >>= 1) {
        s1.x += __shfl_down_sync(0xFFFFFFFFu, s1.x, o);
        s1.y += __shfl_down_sync(0xFFFFFFFFu, s1.y, o);
        s1.z += __shfl_down_sync(0xFFFFFFFFu, s1.z, o);
        s1.w += __shfl_down_sync(0xFFFFFFFFu, s1.w, o);
        s2.x += __shfl_down_sync(0xFFFFFFFFu, s2.x, o);
        s2.y += __shfl_down_sync(0xFFFFFFFFu, s2.y, o);
        s2.z += __shfl_down_sync(0xFFFFFFFFu, s2.z, o);
        s2.w += __shfl_down_sync(0xFFFFFFFFu, s2.w, o);
    }

    __shared__ float4 sh1[8][2], sh2[8][2];    // [warp][col]
    const int warp = t >> 5, lane = t & 31;
    if (lane < 2) { sh1[warp][lane] = s1; sh2[warp][lane] = s2; }
    __syncthreads();

    if (warp == 0 && lane < 16) {
        // lane = w*2 + c, w in 0..7 ; reduce over w with offsets 8,4,2
        const int w = lane >> 1, c = lane & 1;
        float4 v1 = sh1[w][c], v2 = sh2[w][c];
        #pragma unroll
        for (int o = 8; o >= 2; o >>= 1) {
            v1.x += __shfl_down_sync(0x0000FFFFu, v1.x, o, 16);
            v1.y += __shfl_down_sync(0x0000FFFFu, v1.y, o, 16);
            v1.z += __shfl_down_sync(0x0000FFFFu, v1.z, o, 16);
            v1.w += __shfl_down_sync(0x0000FFFFu, v1.w, o, 16);
            v2.x += __shfl_down_sync(0x0000FFFFu, v2.x, o, 16);
            v2.y += __shfl_down_sync(0x0000FFFFu, v2.y, o, 16);
            v2.z += __shfl_down_sync(0x0000FFFFu, v2.z, o, 16);
            v2.w += __shfl_down_sync(0x0000FFFFu, v2.w, o, 16);
        }
        // lanes 0,1 hold COMPLETE colsums for cols g*2+{0,1} -> dot in double
        double d = (double)v1.x * (double)v2.x
                 + (double)v1.y * (double)v2.y
                 + (double)v1.z * (double)v2.z
                 + (double)v1.w * (double)v2.w;
        d += __shfl_down_sync(0x0000FFFFu, d, 1, 16);

        if (lane == 0) {
            atomicAdd(&g_acc, d);
            __threadfence();
            const unsigned dt = atomicAdd(&g_done, 1u);
            if (dt == K2B - 1)
                out[0] = (float)(*(volatile double*)&g_acc * inv_count);
        }
    }
}

extern "C" void kernel_launch(void* const* d_in, const int* in_sizes, int n_in,
                              void* d_out, int out_size)
{
    const float4* x1 = (const float4*)d_in[0];
    const float4* x2 = (const float4*)d_in[1];
    float* out = (float*)d_out;

    const int rows1 = in_sizes[0] / D;   // 8192
    const int rows2 = in_sizes[1] / D;   // 8192
    const double inv_count = 1.0 / ((double)rows1 * (double)rows2);

    colsum_partials<<<NB, 256>>>(x1, x2, rows1);
    reduce_dot_finalize<<<K2B, 256>>>(out, inv_count);
}